// round 13
// baseline (speedup 1.0000x reference)
#include <cuda_runtime.h>
#include <cuda_bf16.h>

// ============================================================================
// TeacherRetrieverPool: weighted RRF fusion + full descending stable argsort.
// Stable argsort(-fused) == [nonzero docs (score desc, doc asc)] ++ [rest asc].
// Outputs are FLOAT32 values. Inputs classified on-device by bit pattern.
//
// R13: single-wave persistent scheme. Grid = B producers + 384 persistent
// fill blocks (148 SMs x 3 resident - producers). Fill blocks grid-stride
// over (batch, chunk) items; spin only on first touch of a batch.
// ============================================================================

#define MAXE 512
#define MAXB 128
#define ND_CONST 1000000
#define PADDOC (1 << 20)

#define FILL_BLK  512
#define WARP_U    1024
#define SUBS      2
#define CHUNK     (16 * SUBS * WARP_U)               // 32768
#define FPB       ((ND_CONST + CHUNK - 1) / CHUNK)   // 31 chunks per batch
#define NFILL     384                                // persistent fill blocks

__device__ int g_th   [MAXB * MAXE];
__device__ int g_cnt  [MAXB];
__device__ int g_ready[MAXB];   // statically zero; self-reset each launch
__device__ int g_done [MAXB];

// ---- dtype-agnostic scalar loads ------------------------------------------
__device__ __forceinline__ int load_as_int(const void* p, long long off, bool is_float) {
    if (is_float) return (int)(((const float*)p)[off] + 0.5f);
    return ((const int*)p)[off];
}
__device__ __forceinline__ float load_as_float(const void* p, long long off, bool is_int) {
    if (is_int) return (float)(((const int*)p)[off]);
    return ((const float*)p)[off];
}
__device__ __forceinline__ int classify(const void* p) {
    const unsigned* u = (const unsigned*)p;
    bool all_small = true;
    int lt1 = 0;
    #pragma unroll
    for (int j = 0; j < 8; ++j) {
        unsigned w = u[j];
        if (w >= (1u << 24)) all_small = false;
        float f = __uint_as_float(w);
        if (fabsf(f) < 1.0f) lt1++;
    }
    if (all_small) return 0;
    return (lt1 >= 6) ? 1 : 2;
}

// ---- 512-elem bitonic sort: shfl for j<=16, shared for j>=32 ---------------
__device__ __forceinline__ unsigned long long
bitonic512(unsigned long long key, unsigned long long* s_key, int tid, int lane)
{
    #pragma unroll
    for (int k = 2; k <= 32; k <<= 1) {
        #pragma unroll
        for (int j = k >> 1; j > 0; j >>= 1) {
            unsigned long long pk = __shfl_xor_sync(0xFFFFFFFFu, key, j);
            bool keepmin = (((tid & k) == 0) == ((lane & j) == 0));
            key = keepmin ? (key < pk ? key : pk) : (key > pk ? key : pk);
        }
    }
    #pragma unroll
    for (int k = 64; k <= 512; k <<= 1) {
        for (int j = k >> 1; j >= 32; j >>= 1) {
            s_key[tid] = key;
            __syncthreads();
            unsigned long long pk = s_key[tid ^ j];
            bool keepmin = (((tid & k) == 0) == ((tid & j) == 0));
            key = keepmin ? (key < pk ? key : pk) : (key > pk ? key : pk);
            __syncthreads();
        }
        #pragma unroll
        for (int j = 16; j > 0; j >>= 1) {
            unsigned long long pk = __shfl_xor_sync(0xFFFFFFFFu, key, j);
            bool keepmin = (((tid & k) == 0) == ((lane & j) == 0));
            key = keepmin ? (key < pk ? key : pk) : (key > pk ? key : pk);
        }
    }
    s_key[tid] = key;
    __syncthreads();
    return key;
}

__device__ __forceinline__ int cnt_le_sh(const int* __restrict__ TH, int x) {
    int c = 0;
    #pragma unroll
    for (int s = MAXE / 2; s > 0; s >>= 1) {
        int t = c + s;
        if (TH[t - 1] <= x) c = t;
    }
    return c;
}

// ---------------------------------------------------------------------------
__global__ void __launch_bounds__(FILL_BLK)
fused_kernel(const void* __restrict__ cand0,
             const void* __restrict__ cand1,
             const void* __restrict__ wgt,
             const void* __restrict__ pos,
             float* __restrict__ order,
             float* __restrict__ positive,
             int T, int K, int ND, int B)
{
    __shared__ union {
        struct {
            unsigned long long key[MAXE];
            int excl[MAXE];
            int wsum[16];
        } p;
        struct {
            int th[MAXE];
            int n;
        } f;
    } sm;

    const int tid  = threadIdx.x;
    const int lane = tid & 31;
    const int warp = tid >> 5;

    if ((int)blockIdx.x < B) {
        // ===================== PRODUCER =====================
        const int b  = blockIdx.x;
        const int TK = T * K;

        int t0 = classify(cand0);
        int t1 = classify(cand1);
        const void* idxp;  bool idx_is_float;
        const void* rnkp;
        if (t0 == 1)      { rnkp = cand0; idxp = cand1; idx_is_float = (t1 == 2); }
        else if (t1 == 1) { rnkp = cand1; idxp = cand0; idx_is_float = (t0 == 2); }
        else              { idxp = (t0 == 0 || t0 == 2) ? cand0 : cand1;
                            rnkp = (idxp == cand0) ? cand1 : cand0;
                            idx_is_float = (classify(idxp) == 2); }
        bool wgt_is_int = (((const unsigned*)wgt)[0] < (1u << 24));
        bool pos_is_int = (((const unsigned*)pos)[0] < (1u << 24));

        unsigned long long key;
        {
            int doc; unsigned sb;
            if (tid < TK) {
                long long off = (long long)b * TK + tid;
                int t = tid / K;
                doc = load_as_int(idxp, off, idx_is_float);
                float w = load_as_float(wgt, t, wgt_is_int);
                float r = ((const float*)rnkp)[off];
                sb = __float_as_uint(w / (60.0f + r));   // RRF_K = 60; > 0
            } else {
                doc = PADDOC; sb = 0u;
            }
            key = ((unsigned long long)(unsigned)doc << 41)
                | ((unsigned long long)(unsigned)tid << 32)
                | (unsigned long long)sb;
        }

        key = bitonic512(key, sm.p.key, tid, lane);   // asc (doc, j)

        int  doc_i = (int)(key >> 41);
        bool head  = (doc_i < PADDOC) &&
                     (tid == 0 || (int)(sm.p.key[tid - 1] >> 41) != doc_i);
        float total = 0.0f;
        if (head) {
            total = __uint_as_float((unsigned)key);
            for (int m = tid + 1; m < MAXE && (int)(sm.p.key[m] >> 41) == doc_i; ++m)
                total += __uint_as_float((unsigned)sm.p.key[m]);
        }

        unsigned bmask = __ballot_sync(0xFFFFFFFFu, head);
        int wr = __popc(bmask & ((1u << lane) - 1));
        if (lane == 0) sm.p.wsum[warp] = __popc(bmask);
        __syncthreads();
        int pre = 0, n = 0;
        #pragma unroll
        for (int w = 0; w < 16; ++w) {
            int v = sm.p.wsum[w];
            if (w < warp) pre += v;
            n += v;
        }
        const int rank = pre + wr;

        sm.p.excl[tid] = 0x7FFFFFFF;
        __syncthreads();
        if (head) sm.p.excl[rank] = doc_i;
        __syncthreads();
        {
            int e = sm.p.excl[tid];
            g_th[b * MAXE + tid] = (e == 0x7FFFFFFF) ? 0x7FFFFFFF : (e - tid);
        }

        int pval = -1;
        if (tid == 0 && positive != nullptr) {
            int p = load_as_int(pos, b, !pos_is_int);
            if (p >= n && p < ND) {
                int u = p - n;
                int c = 0;
                for (int s = MAXE / 2; s > 0; s >>= 1) {
                    int t2 = c + s;
                    int e = sm.p.excl[t2 - 1];
                    int th = (e == 0x7FFFFFFF) ? 0x7FFFFFFF : e - (t2 - 1);
                    if (th <= u) c = t2;
                }
                pval = u + c;
            } else if (p < 0 || p >= ND) {
                pval = 0;
            }
        }
        __syncthreads();

        unsigned long long k2;
        if (head) {
            unsigned sb = __float_as_uint(total);
            k2 = ((unsigned long long)(0xFFFFFFFFu - sb) << 32) | (unsigned)doc_i;
        } else {
            k2 = 0xFFFFFFFFFFFFFFFFull;
        }
        __syncthreads();
        k2 = bitonic512(k2, sm.p.key, tid, lane);     // (score desc, doc asc)

        if (tid < n)
            order[(long long)b * ND + tid] = (float)(unsigned)(k2 & 0xFFFFFFFFull);

        if (tid == 0) {
            g_cnt[b] = n;
            if (positive != nullptr) {
                int p = load_as_int(pos, b, !pos_is_int);
                float v;
                if (p >= 0 && p < n)
                    v = (float)(unsigned)(sm.p.key[p] & 0xFFFFFFFFull);
                else
                    v = (float)pval;
                positive[b] = v;
            }
        }

        __syncthreads();
        __threadfence();
        if (tid == 0) atomicExch(&g_ready[b], 1);

    } else {
        // ============== PERSISTENT FILL (grid-stride over items) ==============
        const int fb    = blockIdx.x - B;
        const int F     = gridDim.x - B;
        const int items = B * FPB;

        for (int w = fb; w < items; w += F) {
            const int b  = w % B;           // spread first items across batches
            const int cx = w / B;
            const int lo = cx * CHUNK;

            if (tid == 0) {
                while (atomicAdd(&g_ready[b], 0) == 0) __nanosleep(200);
            }
            __syncthreads();

            sm.f.th[tid] = g_th[b * MAXE + tid];
            if (tid == 0) sm.f.n = g_cnt[b];
            __syncthreads();

            const int n       = sm.f.n;
            const int tailLen = ND - n;
            float* ob = order + (long long)b * ND;

            #pragma unroll
            for (int r = 0; r < SUBS; ++r) {
                const int u0 = lo + (warp * SUBS + r) * WARP_U;
                if (u0 < tailLen) {
                    const int uEnd = (u0 + WARP_U < tailLen) ? (u0 + WARP_U) : tailLen;

                    const int tLo = cnt_le_sh(sm.f.th, u0 - 1);
                    const int tHi = cnt_le_sh(sm.f.th, uEnd - 1);
                    const int nl  = tHi - tLo;

                    const int q0   = n + u0;
                    const int qEnd = n + uEnd;
                    int qa = (q0 + 3) & ~3;
                    int qb = qEnd & ~3;
                    if (qb < qa) qb = qa;

                    if (lane < qa - q0) {
                        int q = q0 + lane;
                        int u = q - n;
                        int d = u + tLo;
                        for (int e = tLo; e < tHi; ++e) d += (sm.f.th[e] <= u);
                        ob[q] = (float)d;
                    }
                    if (lane >= 4 && lane - 4 < qEnd - qb) {
                        int q = qb + (lane - 4);
                        int u = q - n;
                        int d = u + tLo;
                        for (int e = tLo; e < tHi; ++e) d += (sm.f.th[e] <= u);
                        ob[q] = (float)d;
                    }

                    const int NV = (qb - qa) >> 2;
                    if (nl == 0) {
                        const int base = tLo - n;
                        float f = (float)(qa + (lane << 2) + base);
                        for (int vi = lane; vi < NV; vi += 32) {
                            int q = qa + (vi << 2);
                            float4 o;
                            o.x = f; o.y = f + 1.0f; o.z = f + 2.0f; o.w = f + 3.0f;
                            *(float4*)(ob + q) = o;
                            f += 128.0f;
                        }
                    } else {
                        for (int vi = lane; vi < NV; vi += 32) {
                            int q = qa + (vi << 2);
                            int u = q - n;
                            int d0 = u + tLo, d1 = d0 + 1, d2 = d0 + 2, d3 = d0 + 3;
                            for (int e = tLo; e < tHi; ++e) {
                                int v = sm.f.th[e];
                                d0 += (v <= u);
                                d1 += (v <= u + 1);
                                d2 += (v <= u + 2);
                                d3 += (v <= u + 3);
                            }
                            float4 o;
                            o.x = (float)d0; o.y = (float)d1;
                            o.z = (float)d2; o.w = (float)d3;
                            *(float4*)(ob + q) = o;
                        }
                    }
                }
            }

            // item complete; last chunk of batch b resets flags for next replay
            __syncthreads();
            if (tid == 0) {
                int old = atomicAdd(&g_done[b], 1);
                if (old == FPB - 1) {
                    atomicExch(&g_done[b], 0);
                    atomicExch(&g_ready[b], 0);
                }
            }
        }
    }
}

// ---------------------------------------------------------------------------
// Launch
// ---------------------------------------------------------------------------
extern "C" void kernel_launch(void* const* d_in, const int* in_sizes, int n_in,
                              void* d_out, int out_size)
{
    const long long ND = ND_CONST;

    long long B;
    bool has_positive;
    if ((long long)out_size % (ND + 1) == 0) {
        B = (long long)out_size / (ND + 1);
        has_positive = true;
    } else if ((long long)out_size % ND == 0) {
        B = (long long)out_size / ND;
        has_positive = false;
    } else {
        return;
    }
    if (B <= 0 || B > MAXB) return;

    int maxsz = 0;
    for (int i = 0; i < n_in; ++i) if (in_sizes[i] > maxsz) maxsz = in_sizes[i];
    int iC0 = -1, iC1 = -1;
    for (int i = 0; i < n_in; ++i) {
        if (in_sizes[i] == maxsz) { if (iC0 < 0) iC0 = i; else if (iC1 < 0) iC1 = i; }
    }
    if (iC0 < 0 || iC1 < 0) return;

    int iPos = -1;
    for (int i = 0; i < n_in; ++i) {
        if (i == iC0 || i == iC1) continue;
        if ((long long)in_sizes[i] == B) { iPos = i; break; }
    }
    int iWgt = -1;
    for (int i = 0; i < n_in; ++i) {
        if (i == iC0 || i == iC1 || i == iPos) continue;
        if (in_sizes[i] > 1) { iWgt = i; break; }
    }
    if (iWgt < 0) {
        for (int i = 0; i < n_in; ++i) {
            if (i == iC0 || i == iC1 || i == iPos) continue;
            iWgt = i; break;
        }
    }
    if (iPos < 0 || iWgt < 0) return;

    const int T  = in_sizes[iWgt];
    const int TK = (int)((long long)maxsz / B);
    const int K  = TK / T;
    if (TK > MAXE || T * K != TK || (long long)TK * B != maxsz) return;

    float* order    = (float*)d_out;
    float* positive = has_positive ? (float*)d_out + B * ND : nullptr;

    const unsigned total_blocks = (unsigned)(B + NFILL);
    fused_kernel<<<total_blocks, FILL_BLK>>>(
        d_in[iC0], d_in[iC1], d_in[iWgt], d_in[iPos],
        order, positive, T, K, (int)ND, (int)B);
}

// round 14
// speedup vs baseline: 1.0867x; 1.0867x over previous
#include <cuda_runtime.h>
#include <cuda_bf16.h>

// ============================================================================
// TeacherRetrieverPool: weighted RRF fusion + full descending stable argsort.
// Stable argsort(-fused) == [nonzero docs (score desc, doc asc)] ++ [rest asc].
// Outputs are FLOAT32 values. Inputs classified on-device by bit pattern.
//
// R14: fused producer+fill (R12) with R10's fill geometry: CHUNK=16384,
// one chunk per fill block (oversubscribed grid = B + B*62 blocks).
// ============================================================================

#define MAXE 512
#define MAXB 128
#define ND_CONST 1000000
#define PADDOC (1 << 20)

#define FILL_BLK  512
#define WARP_U    1024
#define CHUNK     (16 * WARP_U)                      // 16384 (16 warps x 1024)
#define FPB       ((ND_CONST + CHUNK - 1) / CHUNK)   // 62 chunks per batch

__device__ int g_th   [MAXB * MAXE];
__device__ int g_cnt  [MAXB];
__device__ int g_ready[MAXB];   // statically zero; self-reset each launch
__device__ int g_done [MAXB];

// ---- dtype-agnostic scalar loads ------------------------------------------
__device__ __forceinline__ int load_as_int(const void* p, long long off, bool is_float) {
    if (is_float) return (int)(((const float*)p)[off] + 0.5f);
    return ((const int*)p)[off];
}
__device__ __forceinline__ float load_as_float(const void* p, long long off, bool is_int) {
    if (is_int) return (float)(((const int*)p)[off]);
    return ((const float*)p)[off];
}
__device__ __forceinline__ int classify(const void* p) {
    const unsigned* u = (const unsigned*)p;
    bool all_small = true;
    int lt1 = 0;
    #pragma unroll
    for (int j = 0; j < 8; ++j) {
        unsigned w = u[j];
        if (w >= (1u << 24)) all_small = false;
        float f = __uint_as_float(w);
        if (fabsf(f) < 1.0f) lt1++;
    }
    if (all_small) return 0;
    return (lt1 >= 6) ? 1 : 2;
}

// ---- 512-elem bitonic sort: shfl for j<=16, shared for j>=32 ---------------
__device__ __forceinline__ unsigned long long
bitonic512(unsigned long long key, unsigned long long* s_key, int tid, int lane)
{
    #pragma unroll
    for (int k = 2; k <= 32; k <<= 1) {
        #pragma unroll
        for (int j = k >> 1; j > 0; j >>= 1) {
            unsigned long long pk = __shfl_xor_sync(0xFFFFFFFFu, key, j);
            bool keepmin = (((tid & k) == 0) == ((lane & j) == 0));
            key = keepmin ? (key < pk ? key : pk) : (key > pk ? key : pk);
        }
    }
    #pragma unroll
    for (int k = 64; k <= 512; k <<= 1) {
        for (int j = k >> 1; j >= 32; j >>= 1) {
            s_key[tid] = key;
            __syncthreads();
            unsigned long long pk = s_key[tid ^ j];
            bool keepmin = (((tid & k) == 0) == ((tid & j) == 0));
            key = keepmin ? (key < pk ? key : pk) : (key > pk ? key : pk);
            __syncthreads();
        }
        #pragma unroll
        for (int j = 16; j > 0; j >>= 1) {
            unsigned long long pk = __shfl_xor_sync(0xFFFFFFFFu, key, j);
            bool keepmin = (((tid & k) == 0) == ((lane & j) == 0));
            key = keepmin ? (key < pk ? key : pk) : (key > pk ? key : pk);
        }
    }
    s_key[tid] = key;
    __syncthreads();
    return key;
}

__device__ __forceinline__ int cnt_le_sh(const int* __restrict__ TH, int x) {
    int c = 0;
    #pragma unroll
    for (int s = MAXE / 2; s > 0; s >>= 1) {
        int t = c + s;
        if (TH[t - 1] <= x) c = t;
    }
    return c;
}

// ---------------------------------------------------------------------------
__global__ void __launch_bounds__(FILL_BLK)
fused_kernel(const void* __restrict__ cand0,
             const void* __restrict__ cand1,
             const void* __restrict__ wgt,
             const void* __restrict__ pos,
             float* __restrict__ order,
             float* __restrict__ positive,
             int T, int K, int ND, int B)
{
    __shared__ union {
        struct {
            unsigned long long key[MAXE];
            int excl[MAXE];
            int wsum[16];
        } p;
        struct {
            int th[MAXE];
            int n;
        } f;
    } sm;

    const int tid  = threadIdx.x;
    const int lane = tid & 31;
    const int warp = tid >> 5;

    if ((int)blockIdx.x < B) {
        // ===================== PRODUCER =====================
        const int b  = blockIdx.x;
        const int TK = T * K;

        int t0 = classify(cand0);
        int t1 = classify(cand1);
        const void* idxp;  bool idx_is_float;
        const void* rnkp;
        if (t0 == 1)      { rnkp = cand0; idxp = cand1; idx_is_float = (t1 == 2); }
        else if (t1 == 1) { rnkp = cand1; idxp = cand0; idx_is_float = (t0 == 2); }
        else              { idxp = (t0 == 0 || t0 == 2) ? cand0 : cand1;
                            rnkp = (idxp == cand0) ? cand1 : cand0;
                            idx_is_float = (classify(idxp) == 2); }
        bool wgt_is_int = (((const unsigned*)wgt)[0] < (1u << 24));
        bool pos_is_int = (((const unsigned*)pos)[0] < (1u << 24));

        unsigned long long key;
        {
            int doc; unsigned sb;
            if (tid < TK) {
                long long off = (long long)b * TK + tid;
                int t = tid / K;
                doc = load_as_int(idxp, off, idx_is_float);
                float w = load_as_float(wgt, t, wgt_is_int);
                float r = ((const float*)rnkp)[off];
                sb = __float_as_uint(w / (60.0f + r));   // RRF_K = 60; > 0
            } else {
                doc = PADDOC; sb = 0u;
            }
            key = ((unsigned long long)(unsigned)doc << 41)
                | ((unsigned long long)(unsigned)tid << 32)
                | (unsigned long long)sb;
        }

        key = bitonic512(key, sm.p.key, tid, lane);   // asc (doc, j)

        int  doc_i = (int)(key >> 41);
        bool head  = (doc_i < PADDOC) &&
                     (tid == 0 || (int)(sm.p.key[tid - 1] >> 41) != doc_i);
        float total = 0.0f;
        if (head) {
            total = __uint_as_float((unsigned)key);
            for (int m = tid + 1; m < MAXE && (int)(sm.p.key[m] >> 41) == doc_i; ++m)
                total += __uint_as_float((unsigned)sm.p.key[m]);
        }

        unsigned bmask = __ballot_sync(0xFFFFFFFFu, head);
        int wr = __popc(bmask & ((1u << lane) - 1));
        if (lane == 0) sm.p.wsum[warp] = __popc(bmask);
        __syncthreads();
        int pre = 0, n = 0;
        #pragma unroll
        for (int w = 0; w < 16; ++w) {
            int v = sm.p.wsum[w];
            if (w < warp) pre += v;
            n += v;
        }
        const int rank = pre + wr;

        sm.p.excl[tid] = 0x7FFFFFFF;
        __syncthreads();
        if (head) sm.p.excl[rank] = doc_i;
        __syncthreads();
        {
            int e = sm.p.excl[tid];
            g_th[b * MAXE + tid] = (e == 0x7FFFFFFF) ? 0x7FFFFFFF : (e - tid);
        }

        int pval = -1;
        if (tid == 0 && positive != nullptr) {
            int p = load_as_int(pos, b, !pos_is_int);
            if (p >= n && p < ND) {
                int u = p - n;
                int c = 0;
                for (int s = MAXE / 2; s > 0; s >>= 1) {
                    int t2 = c + s;
                    int e = sm.p.excl[t2 - 1];
                    int th = (e == 0x7FFFFFFF) ? 0x7FFFFFFF : e - (t2 - 1);
                    if (th <= u) c = t2;
                }
                pval = u + c;
            } else if (p < 0 || p >= ND) {
                pval = 0;
            }
        }
        __syncthreads();

        unsigned long long k2;
        if (head) {
            unsigned sb = __float_as_uint(total);
            k2 = ((unsigned long long)(0xFFFFFFFFu - sb) << 32) | (unsigned)doc_i;
        } else {
            k2 = 0xFFFFFFFFFFFFFFFFull;
        }
        __syncthreads();
        k2 = bitonic512(k2, sm.p.key, tid, lane);     // (score desc, doc asc)

        if (tid < n)
            order[(long long)b * ND + tid] = (float)(unsigned)(k2 & 0xFFFFFFFFull);

        if (tid == 0) {
            g_cnt[b] = n;
            if (positive != nullptr) {
                int p = load_as_int(pos, b, !pos_is_int);
                float v;
                if (p >= 0 && p < n)
                    v = (float)(unsigned)(sm.p.key[p] & 0xFFFFFFFFull);
                else
                    v = (float)pval;
                positive[b] = v;
            }
        }

        __syncthreads();
        __threadfence();
        if (tid == 0) atomicExch(&g_ready[b], 1);

    } else {
        // ===================== FILL (one chunk per block) =====================
        const int fb = blockIdx.x - B;
        const int b  = fb % B;          // adjacent bids -> different batches
        const int cx = fb / B;
        const int lo = cx * CHUNK;

        if (tid == 0) {
            while (atomicAdd(&g_ready[b], 0) == 0) __nanosleep(200);
        }
        __syncthreads();

        sm.f.th[tid] = g_th[b * MAXE + tid];
        if (tid == 0) sm.f.n = g_cnt[b];
        __syncthreads();

        const int n       = sm.f.n;
        const int tailLen = ND - n;
        float* ob = order + (long long)b * ND;

        const int u0 = lo + warp * WARP_U;
        if (u0 < tailLen) {
            const int uEnd = (u0 + WARP_U < tailLen) ? (u0 + WARP_U) : tailLen;

            const int tLo = cnt_le_sh(sm.f.th, u0 - 1);
            const int tHi = cnt_le_sh(sm.f.th, uEnd - 1);
            const int nl  = tHi - tLo;

            const int q0   = n + u0;
            const int qEnd = n + uEnd;
            int qa = (q0 + 3) & ~3;
            int qb = qEnd & ~3;
            if (qb < qa) qb = qa;

            if (lane < qa - q0) {
                int q = q0 + lane;
                int u = q - n;
                int d = u + tLo;
                for (int e = tLo; e < tHi; ++e) d += (sm.f.th[e] <= u);
                ob[q] = (float)d;
            }
            if (lane >= 4 && lane - 4 < qEnd - qb) {
                int q = qb + (lane - 4);
                int u = q - n;
                int d = u + tLo;
                for (int e = tLo; e < tHi; ++e) d += (sm.f.th[e] <= u);
                ob[q] = (float)d;
            }

            const int NV = (qb - qa) >> 2;
            if (nl == 0) {
                const int base = tLo - n;
                float f = (float)(qa + (lane << 2) + base);
                for (int vi = lane; vi < NV; vi += 32) {
                    int q = qa + (vi << 2);
                    float4 o;
                    o.x = f; o.y = f + 1.0f; o.z = f + 2.0f; o.w = f + 3.0f;
                    *(float4*)(ob + q) = o;
                    f += 128.0f;
                }
            } else {
                for (int vi = lane; vi < NV; vi += 32) {
                    int q = qa + (vi << 2);
                    int u = q - n;
                    int d0 = u + tLo, d1 = d0 + 1, d2 = d0 + 2, d3 = d0 + 3;
                    for (int e = tLo; e < tHi; ++e) {
                        int v = sm.f.th[e];
                        d0 += (v <= u);
                        d1 += (v <= u + 1);
                        d2 += (v <= u + 2);
                        d3 += (v <= u + 3);
                    }
                    float4 o;
                    o.x = (float)d0; o.y = (float)d1;
                    o.z = (float)d2; o.w = (float)d3;
                    *(float4*)(ob + q) = o;
                }
            }
        }

        // self-reset: last fill block of batch b clears the flags
        __syncthreads();
        if (tid == 0) {
            int old = atomicAdd(&g_done[b], 1);
            if (old == FPB - 1) {
                atomicExch(&g_done[b], 0);
                atomicExch(&g_ready[b], 0);
            }
        }
    }
}

// ---------------------------------------------------------------------------
// Launch
// ---------------------------------------------------------------------------
extern "C" void kernel_launch(void* const* d_in, const int* in_sizes, int n_in,
                              void* d_out, int out_size)
{
    const long long ND = ND_CONST;

    long long B;
    bool has_positive;
    if ((long long)out_size % (ND + 1) == 0) {
        B = (long long)out_size / (ND + 1);
        has_positive = true;
    } else if ((long long)out_size % ND == 0) {
        B = (long long)out_size / ND;
        has_positive = false;
    } else {
        return;
    }
    if (B <= 0 || B > MAXB) return;

    int maxsz = 0;
    for (int i = 0; i < n_in; ++i) if (in_sizes[i] > maxsz) maxsz = in_sizes[i];
    int iC0 = -1, iC1 = -1;
    for (int i = 0; i < n_in; ++i) {
        if (in_sizes[i] == maxsz) { if (iC0 < 0) iC0 = i; else if (iC1 < 0) iC1 = i; }
    }
    if (iC0 < 0 || iC1 < 0) return;

    int iPos = -1;
    for (int i = 0; i < n_in; ++i) {
        if (i == iC0 || i == iC1) continue;
        if ((long long)in_sizes[i] == B) { iPos = i; break; }
    }
    int iWgt = -1;
    for (int i = 0; i < n_in; ++i) {
        if (i == iC0 || i == iC1 || i == iPos) continue;
        if (in_sizes[i] > 1) { iWgt = i; break; }
    }
    if (iWgt < 0) {
        for (int i = 0; i < n_in; ++i) {
            if (i == iC0 || i == iC1 || i == iPos) continue;
            iWgt = i; break;
        }
    }
    if (iPos < 0 || iWgt < 0) return;

    const int T  = in_sizes[iWgt];
    const int TK = (int)((long long)maxsz / B);
    const int K  = TK / T;
    if (TK > MAXE || T * K != TK || (long long)TK * B != maxsz) return;

    float* order    = (float*)d_out;
    float* positive = has_positive ? (float*)d_out + B * ND : nullptr;

    const unsigned total_blocks = (unsigned)(B + B * FPB);
    fused_kernel<<<total_blocks, FILL_BLK>>>(
        d_in[iC0], d_in[iC1], d_in[iWgt], d_in[iPos],
        order, positive, T, K, (int)ND, (int)B);
}

// round 15
// speedup vs baseline: 1.2172x; 1.1201x over previous
#include <cuda_runtime.h>
#include <cuda_bf16.h>

// ============================================================================
// TeacherRetrieverPool: weighted RRF fusion + full descending stable argsort.
// Stable argsort(-fused) == [nonzero docs (score desc, doc asc)] ++ [rest asc].
// Outputs are FLOAT32 values. Inputs classified on-device by bit pattern.
//
// R15: fused kernel with EARLY RELEASE (flag set after thresholds, before
// sort 2 / head writes -> fill overlaps producer tail) and launch_bounds
// (512,4) to force regs<=32 for 4 blocks/SM store residency.
// ============================================================================

#define MAXE 512
#define MAXB 128
#define ND_CONST 1000000
#define PADDOC (1 << 20)

#define FILL_BLK  512
#define WARP_U    1024
#define CHUNK     (16 * WARP_U)                      // 16384
#define FPB       ((ND_CONST + CHUNK - 1) / CHUNK)   // 62 chunks per batch

__device__ int g_th   [MAXB * MAXE];
__device__ int g_cnt  [MAXB];
__device__ int g_ready[MAXB];   // statically zero; self-reset each launch
__device__ int g_done [MAXB];

// ---- dtype-agnostic scalar loads ------------------------------------------
__device__ __forceinline__ int load_as_int(const void* p, long long off, bool is_float) {
    if (is_float) return (int)(((const float*)p)[off] + 0.5f);
    return ((const int*)p)[off];
}
__device__ __forceinline__ float load_as_float(const void* p, long long off, bool is_int) {
    if (is_int) return (float)(((const int*)p)[off]);
    return ((const float*)p)[off];
}
__device__ __forceinline__ int classify(const void* p) {
    const unsigned* u = (const unsigned*)p;
    bool all_small = true;
    int lt1 = 0;
    #pragma unroll
    for (int j = 0; j < 8; ++j) {
        unsigned w = u[j];
        if (w >= (1u << 24)) all_small = false;
        float f = __uint_as_float(w);
        if (fabsf(f) < 1.0f) lt1++;
    }
    if (all_small) return 0;
    return (lt1 >= 6) ? 1 : 2;
}

// ---- 512-elem bitonic sort: shfl for j<=16, shared for j>=32 ---------------
__device__ __forceinline__ unsigned long long
bitonic512(unsigned long long key, unsigned long long* s_key, int tid, int lane)
{
    #pragma unroll
    for (int k = 2; k <= 32; k <<= 1) {
        #pragma unroll
        for (int j = k >> 1; j > 0; j >>= 1) {
            unsigned long long pk = __shfl_xor_sync(0xFFFFFFFFu, key, j);
            bool keepmin = (((tid & k) == 0) == ((lane & j) == 0));
            key = keepmin ? (key < pk ? key : pk) : (key > pk ? key : pk);
        }
    }
    #pragma unroll
    for (int k = 64; k <= 512; k <<= 1) {
        for (int j = k >> 1; j >= 32; j >>= 1) {
            s_key[tid] = key;
            __syncthreads();
            unsigned long long pk = s_key[tid ^ j];
            bool keepmin = (((tid & k) == 0) == ((tid & j) == 0));
            key = keepmin ? (key < pk ? key : pk) : (key > pk ? key : pk);
            __syncthreads();
        }
        #pragma unroll
        for (int j = 16; j > 0; j >>= 1) {
            unsigned long long pk = __shfl_xor_sync(0xFFFFFFFFu, key, j);
            bool keepmin = (((tid & k) == 0) == ((lane & j) == 0));
            key = keepmin ? (key < pk ? key : pk) : (key > pk ? key : pk);
        }
    }
    s_key[tid] = key;
    __syncthreads();
    return key;
}

__device__ __forceinline__ int cnt_le_sh(const int* __restrict__ TH, int x) {
    int c = 0;
    #pragma unroll
    for (int s = MAXE / 2; s > 0; s >>= 1) {
        int t = c + s;
        if (TH[t - 1] <= x) c = t;
    }
    return c;
}

// ---------------------------------------------------------------------------
__global__ void __launch_bounds__(FILL_BLK, 4)
fused_kernel(const void* __restrict__ cand0,
             const void* __restrict__ cand1,
             const void* __restrict__ wgt,
             const void* __restrict__ pos,
             float* __restrict__ order,
             float* __restrict__ positive,
             int T, int K, int ND, int B)
{
    __shared__ union {
        struct {
            unsigned long long key[MAXE];
            int excl[MAXE];
            int wsum[16];
        } p;
        struct {
            int th[MAXE];
            int n;
        } f;
    } sm;

    const int tid  = threadIdx.x;
    const int lane = tid & 31;
    const int warp = tid >> 5;

    if ((int)blockIdx.x < B) {
        // ===================== PRODUCER =====================
        const int b  = blockIdx.x;
        const int TK = T * K;

        int t0 = classify(cand0);
        int t1 = classify(cand1);
        const void* idxp;  bool idx_is_float;
        const void* rnkp;
        if (t0 == 1)      { rnkp = cand0; idxp = cand1; idx_is_float = (t1 == 2); }
        else if (t1 == 1) { rnkp = cand1; idxp = cand0; idx_is_float = (t0 == 2); }
        else              { idxp = (t0 == 0 || t0 == 2) ? cand0 : cand1;
                            rnkp = (idxp == cand0) ? cand1 : cand0;
                            idx_is_float = (classify(idxp) == 2); }
        bool wgt_is_int = (((const unsigned*)wgt)[0] < (1u << 24));
        bool pos_is_int = (((const unsigned*)pos)[0] < (1u << 24));

        unsigned long long key;
        {
            int doc; unsigned sb;
            if (tid < TK) {
                long long off = (long long)b * TK + tid;
                int t = tid / K;
                doc = load_as_int(idxp, off, idx_is_float);
                float w = load_as_float(wgt, t, wgt_is_int);
                float r = ((const float*)rnkp)[off];
                sb = __float_as_uint(w / (60.0f + r));   // RRF_K = 60; > 0
            } else {
                doc = PADDOC; sb = 0u;
            }
            key = ((unsigned long long)(unsigned)doc << 41)
                | ((unsigned long long)(unsigned)tid << 32)
                | (unsigned long long)sb;
        }

        key = bitonic512(key, sm.p.key, tid, lane);   // asc (doc, j)

        int  doc_i = (int)(key >> 41);
        bool head  = (doc_i < PADDOC) &&
                     (tid == 0 || (int)(sm.p.key[tid - 1] >> 41) != doc_i);
        float total = 0.0f;
        if (head) {
            total = __uint_as_float((unsigned)key);
            for (int m = tid + 1; m < MAXE && (int)(sm.p.key[m] >> 41) == doc_i; ++m)
                total += __uint_as_float((unsigned)sm.p.key[m]);
        }

        unsigned bmask = __ballot_sync(0xFFFFFFFFu, head);
        int wr = __popc(bmask & ((1u << lane) - 1));
        if (lane == 0) sm.p.wsum[warp] = __popc(bmask);
        __syncthreads();
        int pre = 0, n = 0;
        #pragma unroll
        for (int w = 0; w < 16; ++w) {
            int v = sm.p.wsum[w];
            if (w < warp) pre += v;
            n += v;
        }
        const int rank = pre + wr;

        // unique docs ascending -> thresholds; write out, then EARLY RELEASE
        sm.p.excl[tid] = 0x7FFFFFFF;
        __syncthreads();
        if (head) sm.p.excl[rank] = doc_i;
        __syncthreads();
        {
            int e = sm.p.excl[tid];
            g_th[b * MAXE + tid] = (e == 0x7FFFFFFF) ? 0x7FFFFFFF : (e - tid);
        }
        if (tid == 0) g_cnt[b] = n;
        __syncthreads();
        __threadfence();
        if (tid == 0) atomicExch(&g_ready[b], 1);   // fills start NOW

        // ---- remainder overlaps with fill blocks ----
        int pval = -1;
        if (tid == 0 && positive != nullptr) {
            int p = load_as_int(pos, b, !pos_is_int);
            if (p >= n && p < ND) {
                int u = p - n;
                int c = 0;
                for (int s = MAXE / 2; s > 0; s >>= 1) {
                    int t2 = c + s;
                    int e = sm.p.excl[t2 - 1];
                    int th = (e == 0x7FFFFFFF) ? 0x7FFFFFFF : e - (t2 - 1);
                    if (th <= u) c = t2;
                }
                pval = u + c;
            } else if (p < 0 || p >= ND) {
                pval = 0;
            }
        }

        unsigned long long k2;
        if (head) {
            unsigned sb = __float_as_uint(total);
            k2 = ((unsigned long long)(0xFFFFFFFFu - sb) << 32) | (unsigned)doc_i;
        } else {
            k2 = 0xFFFFFFFFFFFFFFFFull;
        }
        __syncthreads();
        k2 = bitonic512(k2, sm.p.key, tid, lane);     // (score desc, doc asc)

        if (tid < n)
            order[(long long)b * ND + tid] = (float)(unsigned)(k2 & 0xFFFFFFFFull);

        if (tid == 0 && positive != nullptr) {
            int p = load_as_int(pos, b, !pos_is_int);
            float v;
            if (p >= 0 && p < n)
                v = (float)(unsigned)(sm.p.key[p] & 0xFFFFFFFFull);
            else
                v = (float)pval;
            positive[b] = v;
        }

    } else {
        // ===================== FILL (one chunk per block) =====================
        const int fb = blockIdx.x - B;
        const int b  = fb % B;          // adjacent bids -> different batches
        const int cx = fb / B;
        const int lo = cx * CHUNK;

        if (tid == 0) {
            while (atomicAdd(&g_ready[b], 0) == 0) __nanosleep(200);
        }
        __syncthreads();

        sm.f.th[tid] = g_th[b * MAXE + tid];
        if (tid == 0) sm.f.n = g_cnt[b];
        __syncthreads();

        const int n       = sm.f.n;
        const int tailLen = ND - n;
        float* ob = order + (long long)b * ND;

        const int u0 = lo + warp * WARP_U;
        if (u0 < tailLen) {
            const int uEnd = (u0 + WARP_U < tailLen) ? (u0 + WARP_U) : tailLen;

            const int tLo = cnt_le_sh(sm.f.th, u0 - 1);
            const int tHi = cnt_le_sh(sm.f.th, uEnd - 1);
            const int nl  = tHi - tLo;

            const int q0   = n + u0;
            const int qEnd = n + uEnd;
            int qa = (q0 + 3) & ~3;
            int qb = qEnd & ~3;
            if (qb < qa) qb = qa;

            if (lane < qa - q0) {
                int q = q0 + lane;
                int u = q - n;
                int d = u + tLo;
                for (int e = tLo; e < tHi; ++e) d += (sm.f.th[e] <= u);
                ob[q] = (float)d;
            }
            if (lane >= 4 && lane - 4 < qEnd - qb) {
                int q = qb + (lane - 4);
                int u = q - n;
                int d = u + tLo;
                for (int e = tLo; e < tHi; ++e) d += (sm.f.th[e] <= u);
                ob[q] = (float)d;
            }

            const int NV = (qb - qa) >> 2;
            if (nl == 0) {
                const int base = tLo - n;
                float f = (float)(qa + (lane << 2) + base);
                for (int vi = lane; vi < NV; vi += 32) {
                    int q = qa + (vi << 2);
                    float4 o;
                    o.x = f; o.y = f + 1.0f; o.z = f + 2.0f; o.w = f + 3.0f;
                    *(float4*)(ob + q) = o;
                    f += 128.0f;
                }
            } else {
                for (int vi = lane; vi < NV; vi += 32) {
                    int q = qa + (vi << 2);
                    int u = q - n;
                    int d0 = u + tLo, d1 = d0 + 1, d2 = d0 + 2, d3 = d0 + 3;
                    for (int e = tLo; e < tHi; ++e) {
                        int v = sm.f.th[e];
                        d0 += (v <= u);
                        d1 += (v <= u + 1);
                        d2 += (v <= u + 2);
                        d3 += (v <= u + 3);
                    }
                    float4 o;
                    o.x = (float)d0; o.y = (float)d1;
                    o.z = (float)d2; o.w = (float)d3;
                    *(float4*)(ob + q) = o;
                }
            }
        }

        // self-reset: last fill block of batch b clears the flags
        __syncthreads();
        if (tid == 0) {
            int old = atomicAdd(&g_done[b], 1);
            if (old == FPB - 1) {
                atomicExch(&g_done[b], 0);
                atomicExch(&g_ready[b], 0);
            }
        }
    }
}

// ---------------------------------------------------------------------------
// Launch
// ---------------------------------------------------------------------------
extern "C" void kernel_launch(void* const* d_in, const int* in_sizes, int n_in,
                              void* d_out, int out_size)
{
    const long long ND = ND_CONST;

    long long B;
    bool has_positive;
    if ((long long)out_size % (ND + 1) == 0) {
        B = (long long)out_size / (ND + 1);
        has_positive = true;
    } else if ((long long)out_size % ND == 0) {
        B = (long long)out_size / ND;
        has_positive = false;
    } else {
        return;
    }
    if (B <= 0 || B > MAXB) return;

    int maxsz = 0;
    for (int i = 0; i < n_in; ++i) if (in_sizes[i] > maxsz) maxsz = in_sizes[i];
    int iC0 = -1, iC1 = -1;
    for (int i = 0; i < n_in; ++i) {
        if (in_sizes[i] == maxsz) { if (iC0 < 0) iC0 = i; else if (iC1 < 0) iC1 = i; }
    }
    if (iC0 < 0 || iC1 < 0) return;

    int iPos = -1;
    for (int i = 0; i < n_in; ++i) {
        if (i == iC0 || i == iC1) continue;
        if ((long long)in_sizes[i] == B) { iPos = i; break; }
    }
    int iWgt = -1;
    for (int i = 0; i < n_in; ++i) {
        if (i == iC0 || i == iC1 || i == iPos) continue;
        if (in_sizes[i] > 1) { iWgt = i; break; }
    }
    if (iWgt < 0) {
        for (int i = 0; i < n_in; ++i) {
            if (i == iC0 || i == iC1 || i == iPos) continue;
            iWgt = i; break;
        }
    }
    if (iPos < 0 || iWgt < 0) return;

    const int T  = in_sizes[iWgt];
    const int TK = (int)((long long)maxsz / B);
    const int K  = TK / T;
    if (TK > MAXE || T * K != TK || (long long)TK * B != maxsz) return;

    float* order    = (float*)d_out;
    float* positive = has_positive ? (float*)d_out + B * ND : nullptr;

    const unsigned total_blocks = (unsigned)(B + B * FPB);
    fused_kernel<<<total_blocks, FILL_BLK>>>(
        d_in[iC0], d_in[iC1], d_in[iWgt], d_in[iPos],
        order, positive, T, K, (int)ND, (int)B);
}

// round 16
// speedup vs baseline: 1.2344x; 1.0142x over previous
#include <cuda_runtime.h>
#include <cuda_bf16.h>

// ============================================================================
// TeacherRetrieverPool: weighted RRF fusion + full descending stable argsort.
// Stable argsort(-fused) == [nonzero docs (score desc, doc asc)] ++ [rest asc].
// Outputs are FLOAT32 values. Inputs classified on-device by bit pattern.
//
// R16: producer speculative parallel loads (classify no longer gates the main
// data loads) + __stcs streaming stores in the fill path. Structure from R15
// (early release, launch_bounds(512,4), CHUNK=16384).
// ============================================================================

#define MAXE 512
#define MAXB 128
#define ND_CONST 1000000
#define PADDOC (1 << 20)

#define FILL_BLK  512
#define WARP_U    1024
#define CHUNK     (16 * WARP_U)                      // 16384
#define FPB       ((ND_CONST + CHUNK - 1) / CHUNK)   // 62 chunks per batch

__device__ int g_th   [MAXB * MAXE];
__device__ int g_cnt  [MAXB];
__device__ int g_ready[MAXB];   // statically zero; self-reset each launch
__device__ int g_done [MAXB];

__device__ __forceinline__ int classify(const void* p) {
    const unsigned* u = (const unsigned*)p;
    bool all_small = true;
    int lt1 = 0;
    #pragma unroll
    for (int j = 0; j < 8; ++j) {
        unsigned w = u[j];
        if (w >= (1u << 24)) all_small = false;
        float f = __uint_as_float(w);
        if (fabsf(f) < 1.0f) lt1++;
    }
    if (all_small) return 0;
    return (lt1 >= 6) ? 1 : 2;
}

// ---- 512-elem bitonic sort: shfl for j<=16, shared for j>=32 ---------------
__device__ __forceinline__ unsigned long long
bitonic512(unsigned long long key, unsigned long long* s_key, int tid, int lane)
{
    #pragma unroll
    for (int k = 2; k <= 32; k <<= 1) {
        #pragma unroll
        for (int j = k >> 1; j > 0; j >>= 1) {
            unsigned long long pk = __shfl_xor_sync(0xFFFFFFFFu, key, j);
            bool keepmin = (((tid & k) == 0) == ((lane & j) == 0));
            key = keepmin ? (key < pk ? key : pk) : (key > pk ? key : pk);
        }
    }
    #pragma unroll
    for (int k = 64; k <= 512; k <<= 1) {
        for (int j = k >> 1; j >= 32; j >>= 1) {
            s_key[tid] = key;
            __syncthreads();
            unsigned long long pk = s_key[tid ^ j];
            bool keepmin = (((tid & k) == 0) == ((tid & j) == 0));
            key = keepmin ? (key < pk ? key : pk) : (key > pk ? key : pk);
            __syncthreads();
        }
        #pragma unroll
        for (int j = 16; j > 0; j >>= 1) {
            unsigned long long pk = __shfl_xor_sync(0xFFFFFFFFu, key, j);
            bool keepmin = (((tid & k) == 0) == ((lane & j) == 0));
            key = keepmin ? (key < pk ? key : pk) : (key > pk ? key : pk);
        }
    }
    s_key[tid] = key;
    __syncthreads();
    return key;
}

__device__ __forceinline__ int cnt_le_sh(const int* __restrict__ TH, int x) {
    int c = 0;
    #pragma unroll
    for (int s = MAXE / 2; s > 0; s >>= 1) {
        int t = c + s;
        if (TH[t - 1] <= x) c = t;
    }
    return c;
}

// ---------------------------------------------------------------------------
__global__ void __launch_bounds__(FILL_BLK, 4)
fused_kernel(const void* __restrict__ cand0,
             const void* __restrict__ cand1,
             const void* __restrict__ wgt,
             const void* __restrict__ pos,
             float* __restrict__ order,
             float* __restrict__ positive,
             int T, int K, int ND, int B)
{
    __shared__ union {
        struct {
            unsigned long long key[MAXE];
            int excl[MAXE];
            int wsum[16];
        } p;
        struct {
            int th[MAXE];
            int n;
        } f;
    } sm;

    const int tid  = threadIdx.x;
    const int lane = tid & 31;
    const int warp = tid >> 5;

    if ((int)blockIdx.x < B) {
        // ===================== PRODUCER =====================
        const int b  = blockIdx.x;
        const int TK = T * K;

        // --- speculative loads: issue BOTH candidates + weight word now ---
        unsigned c0v = 0, c1v = 0, wraw = 0;
        if (tid < TK) {
            long long off = (long long)b * TK + tid;
            c0v  = ((const unsigned*)cand0)[off];
            c1v  = ((const unsigned*)cand1)[off];
            wraw = ((const unsigned*)wgt)[tid / K];
        }
        // --- classify overlaps the loads above (independent probe loads) ---
        int t0 = classify(cand0);
        int t1 = classify(cand1);
        bool c0_is_rank;
        bool idx_is_float;
        if (t0 == 1)      { c0_is_rank = true;  idx_is_float = (t1 == 2); }
        else if (t1 == 1) { c0_is_rank = false; idx_is_float = (t0 == 2); }
        else              { c0_is_rank = !(t0 == 0 || t0 == 2);
                            idx_is_float = ((c0_is_rank ? t1 : t0) == 2); }
        bool wgt_is_int = (((const unsigned*)wgt)[0] < (1u << 24));
        bool pos_is_int = (((const unsigned*)pos)[0] < (1u << 24));

        unsigned long long key;
        {
            int doc; unsigned sb;
            if (tid < TK) {
                unsigned dbits = c0_is_rank ? c1v : c0v;
                unsigned rbits = c0_is_rank ? c0v : c1v;
                doc = idx_is_float ? (int)(__uint_as_float(dbits) + 0.5f)
                                   : (int)dbits;
                float w = wgt_is_int ? (float)(int)wraw : __uint_as_float(wraw);
                float r = __uint_as_float(rbits);
                sb = __float_as_uint(w / (60.0f + r));   // RRF_K = 60; > 0
            } else {
                doc = PADDOC; sb = 0u;
            }
            key = ((unsigned long long)(unsigned)doc << 41)
                | ((unsigned long long)(unsigned)tid << 32)
                | (unsigned long long)sb;
        }

        key = bitonic512(key, sm.p.key, tid, lane);   // asc (doc, j)

        int  doc_i = (int)(key >> 41);
        bool head  = (doc_i < PADDOC) &&
                     (tid == 0 || (int)(sm.p.key[tid - 1] >> 41) != doc_i);
        float total = 0.0f;
        if (head) {
            total = __uint_as_float((unsigned)key);
            for (int m = tid + 1; m < MAXE && (int)(sm.p.key[m] >> 41) == doc_i; ++m)
                total += __uint_as_float((unsigned)sm.p.key[m]);
        }

        unsigned bmask = __ballot_sync(0xFFFFFFFFu, head);
        int wr = __popc(bmask & ((1u << lane) - 1));
        if (lane == 0) sm.p.wsum[warp] = __popc(bmask);
        __syncthreads();
        int pre = 0, n = 0;
        #pragma unroll
        for (int w = 0; w < 16; ++w) {
            int v = sm.p.wsum[w];
            if (w < warp) pre += v;
            n += v;
        }
        const int rank = pre + wr;

        // unique docs ascending -> thresholds; write out, then EARLY RELEASE
        sm.p.excl[tid] = 0x7FFFFFFF;
        __syncthreads();
        if (head) sm.p.excl[rank] = doc_i;
        __syncthreads();
        {
            int e = sm.p.excl[tid];
            g_th[b * MAXE + tid] = (e == 0x7FFFFFFF) ? 0x7FFFFFFF : (e - tid);
        }
        if (tid == 0) g_cnt[b] = n;
        __syncthreads();
        __threadfence();
        if (tid == 0) atomicExch(&g_ready[b], 1);   // fills start NOW

        // ---- remainder overlaps with fill blocks ----
        int pval = -1;
        if (tid == 0 && positive != nullptr) {
            unsigned praw = ((const unsigned*)pos)[b];
            int p = pos_is_int ? (int)praw : (int)(__uint_as_float(praw) + 0.5f);
            if (p >= n && p < ND) {
                int u = p - n;
                int c = 0;
                for (int s = MAXE / 2; s > 0; s >>= 1) {
                    int t2 = c + s;
                    int e = sm.p.excl[t2 - 1];
                    int th = (e == 0x7FFFFFFF) ? 0x7FFFFFFF : e - (t2 - 1);
                    if (th <= u) c = t2;
                }
                pval = u + c;
            } else if (p < 0 || p >= ND) {
                pval = 0;
            }
        }

        unsigned long long k2;
        if (head) {
            unsigned sb = __float_as_uint(total);
            k2 = ((unsigned long long)(0xFFFFFFFFu - sb) << 32) | (unsigned)doc_i;
        } else {
            k2 = 0xFFFFFFFFFFFFFFFFull;
        }
        __syncthreads();
        k2 = bitonic512(k2, sm.p.key, tid, lane);     // (score desc, doc asc)

        if (tid < n)
            order[(long long)b * ND + tid] = (float)(unsigned)(k2 & 0xFFFFFFFFull);

        if (tid == 0 && positive != nullptr) {
            unsigned praw = ((const unsigned*)pos)[b];
            int p = pos_is_int ? (int)praw : (int)(__uint_as_float(praw) + 0.5f);
            float v;
            if (p >= 0 && p < n)
                v = (float)(unsigned)(sm.p.key[p] & 0xFFFFFFFFull);
            else
                v = (float)pval;
            positive[b] = v;
        }

    } else {
        // ===================== FILL (one chunk per block) =====================
        const int fb = blockIdx.x - B;
        const int b  = fb % B;          // adjacent bids -> different batches
        const int cx = fb / B;
        const int lo = cx * CHUNK;

        if (tid == 0) {
            while (atomicAdd(&g_ready[b], 0) == 0) __nanosleep(200);
        }
        __syncthreads();

        sm.f.th[tid] = g_th[b * MAXE + tid];
        if (tid == 0) sm.f.n = g_cnt[b];
        __syncthreads();

        const int n       = sm.f.n;
        const int tailLen = ND - n;
        float* ob = order + (long long)b * ND;

        const int u0 = lo + warp * WARP_U;
        if (u0 < tailLen) {
            const int uEnd = (u0 + WARP_U < tailLen) ? (u0 + WARP_U) : tailLen;

            const int tLo = cnt_le_sh(sm.f.th, u0 - 1);
            const int tHi = cnt_le_sh(sm.f.th, uEnd - 1);
            const int nl  = tHi - tLo;

            const int q0   = n + u0;
            const int qEnd = n + uEnd;
            int qa = (q0 + 3) & ~3;
            int qb = qEnd & ~3;
            if (qb < qa) qb = qa;

            if (lane < qa - q0) {
                int q = q0 + lane;
                int u = q - n;
                int d = u + tLo;
                for (int e = tLo; e < tHi; ++e) d += (sm.f.th[e] <= u);
                ob[q] = (float)d;
            }
            if (lane >= 4 && lane - 4 < qEnd - qb) {
                int q = qb + (lane - 4);
                int u = q - n;
                int d = u + tLo;
                for (int e = tLo; e < tHi; ++e) d += (sm.f.th[e] <= u);
                ob[q] = (float)d;
            }

            const int NV = (qb - qa) >> 2;
            if (nl == 0) {
                const int base = tLo - n;
                float f = (float)(qa + (lane << 2) + base);
                for (int vi = lane; vi < NV; vi += 32) {
                    int q = qa + (vi << 2);
                    float4 o;
                    o.x = f; o.y = f + 1.0f; o.z = f + 2.0f; o.w = f + 3.0f;
                    __stcs(reinterpret_cast<float4*>(ob + q), o);
                    f += 128.0f;
                }
            } else {
                for (int vi = lane; vi < NV; vi += 32) {
                    int q = qa + (vi << 2);
                    int u = q - n;
                    int d0 = u + tLo, d1 = d0 + 1, d2 = d0 + 2, d3 = d0 + 3;
                    for (int e = tLo; e < tHi; ++e) {
                        int v = sm.f.th[e];
                        d0 += (v <= u);
                        d1 += (v <= u + 1);
                        d2 += (v <= u + 2);
                        d3 += (v <= u + 3);
                    }
                    float4 o;
                    o.x = (float)d0; o.y = (float)d1;
                    o.z = (float)d2; o.w = (float)d3;
                    __stcs(reinterpret_cast<float4*>(ob + q), o);
                }
            }
        }

        // self-reset: last fill block of batch b clears the flags
        __syncthreads();
        if (tid == 0) {
            int old = atomicAdd(&g_done[b], 1);
            if (old == FPB - 1) {
                atomicExch(&g_done[b], 0);
                atomicExch(&g_ready[b], 0);
            }
        }
    }
}

// ---------------------------------------------------------------------------
// Launch
// ---------------------------------------------------------------------------
extern "C" void kernel_launch(void* const* d_in, const int* in_sizes, int n_in,
                              void* d_out, int out_size)
{
    const long long ND = ND_CONST;

    long long B;
    bool has_positive;
    if ((long long)out_size % (ND + 1) == 0) {
        B = (long long)out_size / (ND + 1);
        has_positive = true;
    } else if ((long long)out_size % ND == 0) {
        B = (long long)out_size / ND;
        has_positive = false;
    } else {
        return;
    }
    if (B <= 0 || B > MAXB) return;

    int maxsz = 0;
    for (int i = 0; i < n_in; ++i) if (in_sizes[i] > maxsz) maxsz = in_sizes[i];
    int iC0 = -1, iC1 = -1;
    for (int i = 0; i < n_in; ++i) {
        if (in_sizes[i] == maxsz) { if (iC0 < 0) iC0 = i; else if (iC1 < 0) iC1 = i; }
    }
    if (iC0 < 0 || iC1 < 0) return;

    int iPos = -1;
    for (int i = 0; i < n_in; ++i) {
        if (i == iC0 || i == iC1) continue;
        if ((long long)in_sizes[i] == B) { iPos = i; break; }
    }
    int iWgt = -1;
    for (int i = 0; i < n_in; ++i) {
        if (i == iC0 || i == iC1 || i == iPos) continue;
        if (in_sizes[i] > 1) { iWgt = i; break; }
    }
    if (iWgt < 0) {
        for (int i = 0; i < n_in; ++i) {
            if (i == iC0 || i == iC1 || i == iPos) continue;
            iWgt = i; break;
        }
    }
    if (iPos < 0 || iWgt < 0) return;

    const int T  = in_sizes[iWgt];
    const int TK = (int)((long long)maxsz / B);
    const int K  = TK / T;
    if (TK > MAXE || T * K != TK || (long long)TK * B != maxsz) return;

    float* order    = (float*)d_out;
    float* positive = has_positive ? (float*)d_out + B * ND : nullptr;

    const unsigned total_blocks = (unsigned)(B + B * FPB);
    fused_kernel<<<total_blocks, FILL_BLK>>>(
        d_in[iC0], d_in[iC1], d_in[iWgt], d_in[iPos],
        order, positive, T, K, (int)ND, (int)B);
}